// round 13
// baseline (speedup 1.0000x reference)
#include <cuda_runtime.h>
#include <cstdint>

#define N_ATOMS 50000
#define M_NBR   12
#define N_ROWS  (N_ATOMS * M_NBR)
#define BN_EPS  1e-5f
#define NB_B    456              // persistent kernelB blocks: 152 SMs x 3 CTAs
#define NB_HALF 228              // blocks per column-half

// ---------------- scratch (device globals; no allocation) ----------------
__device__ float  g_P[(size_t)N_ATOMS * 512];       // [i][0:256)=atom@W1+bias, [256:512)=atom@W2
__device__ float  g_gated[(size_t)N_ROWS * 256];    // pre-BN gated features (active rows only)
__device__ float  g_nbrsum[(size_t)N_ATOMS * 128];
__device__ float  g_stats1[513];                    // S[256], SS[256], cnt
__device__ float  g_stats2[256];                    // S2[128], SS2[128]
__device__ int    g_rows[N_ROWS];                   // compacted active row indices
__device__ int    g_nactive;

#define SMEM_A_BYTES (98304)     // gemmA: s_a 32KB + 2x s_w 32KB
#define SMEM_B_BYTES (68096)     // kernelB: W3half 32KB + 2x V 16KB + meta 1.5KB + stats 1KB

// ---------------- f32x2 / async helpers ----------------
__device__ __forceinline__ uint64_t dup2(float x) {
    uint64_t r; asm("mov.b64 %0, {%1, %1};" : "=l"(r) : "f"(x)); return r;
}
__device__ __forceinline__ void fma2(uint64_t& d, uint64_t a, uint64_t b) {
    asm("fma.rn.f32x2 %0, %1, %2, %0;" : "+l"(d) : "l"(a), "l"(b));
}
__device__ __forceinline__ float lo32(uint64_t v) { return __uint_as_float((unsigned)(v & 0xffffffffu)); }
__device__ __forceinline__ float hi32(uint64_t v) { return __uint_as_float((unsigned)(v >> 32)); }

__device__ __forceinline__ void cpasync16(const float* smem_dst, const float* gsrc) {
    uint32_t sa = (uint32_t)__cvta_generic_to_shared(smem_dst);
    asm volatile("cp.async.cg.shared.global [%0], [%1], 16;" :: "r"(sa), "l"(gsrc));
}
__device__ __forceinline__ void cpasync_commit() { asm volatile("cp.async.commit_group;"); }
__device__ __forceinline__ void cpasync_wait0()  { asm volatile("cp.async.wait_group 0;"); }

__device__ __forceinline__ float sigmoid_fast(float x) {
    float z = __expf(-fabsf(x));
    return __fdividef((x >= 0.f) ? 1.f : z, 1.f + z);
}
__device__ __forceinline__ float softplus_fast(float x) {
    return fmaxf(x, 0.f) + __logf(1.f + __expf(-fabsf(x)));
}

// ---------------- kernel 0: zero stats ----------------
__global__ void zero_stats_kernel() {
    int t = threadIdx.x;
    if (t < 513) g_stats1[t] = 0.f;
    if (t < 256) g_stats2[t] = 0.f;
    if (t == 0)  g_nactive = 0;
}

// ---------------- kernel C: compact active rows ----------------
__global__ void compact_kernel(const float* __restrict__ mask) {
    int t = blockIdx.x * 256 + threadIdx.x;
    bool in = (t < N_ROWS) && (mask[t] != 0.f);
    unsigned b = __ballot_sync(0xffffffffu, in);
    int lane = threadIdx.x & 31;
    int cnt = __popc(b);
    int base = 0;
    if (lane == 0 && cnt) {
        base = atomicAdd(&g_nactive, cnt);
        atomicAdd(&g_stats1[512], (float)cnt);
    }
    base = __shfl_sync(0xffffffffu, base, 0);
    if (in) g_rows[base + __popc(b & ((1u << lane) - 1u))] = t;
}

// ---------------- kernel A: P = atom @ [W1|W2] + bias-fold ----
// Grid (782, 2): 64 rows x 256 cols; A staged once; W in 4 chunks of 32k,
// double-buffered via cp.async (LDGSTS) so chunk loads hide under the mainloop.
__global__ void __launch_bounds__(256, 2) gemmA_kernel(
    const float* __restrict__ atom, const float* __restrict__ W,
    const float* __restrict__ bias)
{
    extern __shared__ float smem[];
    float* s_a  = smem;                 // [k][r] 128x64 (32KB)
    float* s_wb = smem + 128 * 64;      // 2 x [kk][c] 32x256 (2x32KB)

    const int tid  = threadIdx.x;
    const int row0 = blockIdx.x * 64;
    const int h    = blockIdx.y;

    const int rg = tid >> 5;
    const int cx = tid & 31;

    // issue async load of W chunk 0 into buffer 0 (overlaps A staging)
    #pragma unroll
    for (int i = 0; i < 8; i++) {
        int e  = tid + 256 * i;                 // 0..2047 float4s
        int kk = e >> 6;
        int c4 = (e & 63) * 4;
        cpasync16(s_wb + kk * 256 + c4, W + (size_t)(h * 128 + kk) * 256 + c4);
    }
    cpasync_commit();

    // stage full A tile: 64 rows x 128 k, transposed
    for (int t = tid; t < 2048; t += 256) {
        int r  = t & 63;
        int kq = t >> 6;
        float4 v = make_float4(0.f, 0.f, 0.f, 0.f);
        int gr = row0 + r;
        if (gr < N_ATOMS) v = *(const float4*)(atom + (size_t)gr * 128 + kq * 4);
        s_a[(kq * 4 + 0) * 64 + r] = v.x;
        s_a[(kq * 4 + 1) * 64 + r] = v.y;
        s_a[(kq * 4 + 2) * 64 + r] = v.z;
        s_a[(kq * 4 + 3) * 64 + r] = v.w;
    }
    cpasync_wait0();
    __syncthreads();

    uint64_t acc[8][4];
    #pragma unroll
    for (int r = 0; r < 8; r++)
        #pragma unroll
        for (int j = 0; j < 4; j++) acc[r][j] = 0ull;

    int buf = 0;
    for (int chunk = 0; chunk < 4; chunk++) {
        // prefetch next W chunk into spare buffer
        if (chunk < 3) {
            const float* wsrc = W + (size_t)(h * 128 + (chunk + 1) * 32) * 256;
            float* wdst = s_wb + (buf ^ 1) * 8192;
            #pragma unroll
            for (int i = 0; i < 8; i++) {
                int e  = tid + 256 * i;
                int kk = e >> 6;
                int c4 = (e & 63) * 4;
                cpasync16(wdst + kk * 256 + c4, wsrc + (size_t)kk * 256 + c4);
            }
            cpasync_commit();
        }

        const int k0 = chunk * 32;
        const float* sw = s_wb + buf * 8192;
        #pragma unroll 4
        for (int kk = 0; kk < 32; kk++) {
            const float* sa = s_a + (k0 + kk) * 64 + rg * 8;
            float4 a03 = *(const float4*)(sa);
            float4 a47 = *(const float4*)(sa + 4);
            uint64_t ad[8] = { dup2(a03.x), dup2(a03.y), dup2(a03.z), dup2(a03.w),
                               dup2(a47.x), dup2(a47.y), dup2(a47.z), dup2(a47.w) };
            ulonglong2 w01 = *(const ulonglong2*)(sw + kk * 256 + 4 * cx);
            ulonglong2 w23 = *(const ulonglong2*)(sw + kk * 256 + 4 * cx + 128);
            uint64_t wp[4] = { w01.x, w01.y, w23.x, w23.y };
            #pragma unroll
            for (int r = 0; r < 8; r++)
                #pragma unroll
                for (int j = 0; j < 4; j++)
                    fma2(acc[r][j], ad[r], wp[j]);
        }
        cpasync_wait0();
        __syncthreads();
        buf ^= 1;
    }

    float4 ba = make_float4(0.f, 0.f, 0.f, 0.f), bb = ba;
    if (h == 0) {
        ba = *(const float4*)(bias + 4 * cx);
        bb = *(const float4*)(bias + 4 * cx + 128);
    }

    #pragma unroll
    for (int r = 0; r < 8; r++) {
        int row = row0 + rg * 8 + r;
        if (row >= N_ATOMS) break;
        float* dst = g_P + (size_t)row * 512 + h * 256;
        float4 va = make_float4(lo32(acc[r][0]) + ba.x, hi32(acc[r][0]) + ba.y,
                                lo32(acc[r][1]) + ba.z, hi32(acc[r][1]) + ba.w);
        float4 vb = make_float4(lo32(acc[r][2]) + bb.x, hi32(acc[r][2]) + bb.y,
                                lo32(acc[r][3]) + bb.z, hi32(acc[r][3]) + bb.w);
        *(float4*)(dst + 4 * cx)       = va;
        *(float4*)(dst + 4 * cx + 128) = vb;
    }
}

// ---------------- kernel B (PERSISTENT, col-half): gated = nbr@W3 + P1(+b) + P2[idx] ----
// 456 blocks (3/SM). Block = (column-half ch, tile stream). W3-half (32KB) staged
// once; 64-row V tiles double-buffered with register prefetch. acc 8r x 4c = 32 regs.
__global__ void __launch_bounds__(256, 3) kernelB(
    const float* __restrict__ nbr, const int* __restrict__ idx,
    const float* __restrict__ W)
{
    extern __shared__ float smem[];
    float* s_w  = smem;                          // [k][c] 64x128 (32KB)
    float* s_vb = smem + 64 * 128;               // 2 x [k][r] 64x64 (2x16KB)
    int*   s_mt = (int*)(s_vb + 2 * 64 * 64);    // 2 x {row[64], atom[64], idx[64]}
    float* s_st = (float*)(s_mt + 2 * 192);      // S[128], SS[128] (local cols)

    const int tid = threadIdx.x;
    const int na  = g_nactive;
    const int rg  = tid >> 5;
    const int cx  = tid & 31;
    const int ch  = blockIdx.x & 1;              // column half

    // stage W3 half once: 64 k x 128 c
    #pragma unroll
    for (int i = 0; i < 8; i++) {
        int e  = tid + 256 * i;                  // 0..2047 float4s
        int k  = e >> 5;
        int c4 = (e & 31) * 4;
        *(float4*)(s_w + k * 128 + c4) =
            *(const float4*)(W + (size_t)(256 + k) * 256 + ch * 128 + c4);
    }
    if (tid < 128) { s_st[tid] = 0.f; s_st[128 + tid] = 0.f; }

    // prologue: stage meta + V for first tile into buffer 0
    int tile = blockIdx.x >> 1;
    if (tile * 64 < na) {
        int slot0 = tile * 64;
        if (tid < 64) {
            int slot = slot0 + tid;
            int gr = (slot < na) ? g_rows[slot] : -1;
            s_mt[tid]       = gr;
            s_mt[64 + tid]  = (gr >= 0) ? (gr / 12) : 0;
            s_mt[128 + tid] = (gr >= 0) ? idx[gr] : 0;
        }
        #pragma unroll
        for (int j = 0; j < 4; j++) {
            int tt = tid + 256 * j;
            int r = tt & 63, kq = tt >> 6;
            int slot = slot0 + r;
            int gr = (slot < na) ? g_rows[slot] : -1;
            float4 v = make_float4(0.f, 0.f, 0.f, 0.f);
            if (gr >= 0) v = *(const float4*)(nbr + (size_t)gr * 64 + kq * 4);
            s_vb[(kq * 4 + 0) * 64 + r] = v.x;
            s_vb[(kq * 4 + 1) * 64 + r] = v.y;
            s_vb[(kq * 4 + 2) * 64 + r] = v.z;
            s_vb[(kq * 4 + 3) * 64 + r] = v.w;
        }
    }
    __syncthreads();

    int buf = 0;
    for (; tile * 64 < na; tile += NB_HALF) {
        const int  ntile   = tile + NB_HALF;
        const bool hasnext = (ntile * 64 < na);

        // prefetch next tile: meta -> spare bank, V -> registers
        float4 pv0, pv1, pv2, pv3;
        if (hasnext) {
            int slot0n = ntile * 64;
            if (tid < 64) {
                int slot = slot0n + tid;
                int gr = (slot < na) ? g_rows[slot] : -1;
                int* mt = s_mt + (buf ^ 1) * 192;
                mt[tid]       = gr;
                mt[64 + tid]  = (gr >= 0) ? (gr / 12) : 0;
                mt[128 + tid] = (gr >= 0) ? idx[gr] : 0;
            }
            #pragma unroll
            for (int j = 0; j < 4; j++) {
                int tt = tid + 256 * j;
                int r = tt & 63, kq = tt >> 6;
                int slot = slot0n + r;
                int gr = (slot < na) ? g_rows[slot] : -1;
                float4 v = make_float4(0.f, 0.f, 0.f, 0.f);
                if (gr >= 0) v = *(const float4*)(nbr + (size_t)gr * 64 + kq * 4);
                if (j == 0) pv0 = v; else if (j == 1) pv1 = v;
                else if (j == 2) pv2 = v; else pv3 = v;
            }
        }

        // mainloop on current buffer: acc 8 rows x 4 cols (2 pair-accs)
        const float* sv = s_vb + buf * 4096;
        uint64_t acc[8][2];
        #pragma unroll
        for (int r = 0; r < 8; r++) { acc[r][0] = 0ull; acc[r][1] = 0ull; }

        #pragma unroll 4
        for (int k = 0; k < 64; k++) {
            const float* svk = sv + k * 64 + rg * 8;
            float4 a03 = *(const float4*)(svk);
            float4 a47 = *(const float4*)(svk + 4);
            uint64_t ad[8] = { dup2(a03.x), dup2(a03.y), dup2(a03.z), dup2(a03.w),
                               dup2(a47.x), dup2(a47.y), dup2(a47.z), dup2(a47.w) };
            ulonglong2 w01 = *(const ulonglong2*)(s_w + k * 128 + 4 * cx);
            #pragma unroll
            for (int r = 0; r < 8; r++) {
                fma2(acc[r][0], ad[r], w01.x);
                fma2(acc[r][1], ad[r], w01.y);
            }
        }

        // store prefetched V into spare buffer
        if (hasnext) {
            float* dv = s_vb + (buf ^ 1) * 4096;
            #pragma unroll
            for (int j = 0; j < 4; j++) {
                int tt = tid + 256 * j;
                int r = tt & 63, kq = tt >> 6;
                float4 v = (j == 0) ? pv0 : (j == 1) ? pv1 : (j == 2) ? pv2 : pv3;
                dv[(kq * 4 + 0) * 64 + r] = v.x;
                dv[(kq * 4 + 1) * 64 + r] = v.y;
                dv[(kq * 4 + 2) * 64 + r] = v.z;
                dv[(kq * 4 + 3) * 64 + r] = v.w;
            }
        }

        // epilogue: add P1(+bias) + P2[idx], float4 stores, smem stats
        const int* mt    = s_mt + buf * 192;
        const int  slot0 = tile * 64;
        float sq[4] = {0,0,0,0}, ss[4] = {0,0,0,0};

        #pragma unroll
        for (int r = 0; r < 8; r++) {
            int rr   = rg * 8 + r;
            int slot = slot0 + rr;
            if (slot >= na) break;
            int gr = mt[rr];
            const float* P1 = g_P + (size_t)mt[64 + rr] * 512 + ch * 128;
            const float* P2 = g_P + (size_t)mt[128 + rr] * 512 + 256 + ch * 128;
            float4 p1 = *(const float4*)(P1 + 4 * cx);
            float4 p2 = *(const float4*)(P2 + 4 * cx);
            float4 va = make_float4(lo32(acc[r][0]) + p1.x + p2.x,
                                    hi32(acc[r][0]) + p1.y + p2.y,
                                    lo32(acc[r][1]) + p1.z + p2.z,
                                    hi32(acc[r][1]) + p1.w + p2.w);
            *(float4*)(g_gated + (size_t)gr * 256 + ch * 128 + 4 * cx) = va;
            sq[0] += va.x; sq[1] += va.y; sq[2] += va.z; sq[3] += va.w;
            ss[0] = fmaf(va.x, va.x, ss[0]); ss[1] = fmaf(va.y, va.y, ss[1]);
            ss[2] = fmaf(va.z, va.z, ss[2]); ss[3] = fmaf(va.w, va.w, ss[3]);
        }
        #pragma unroll
        for (int t = 0; t < 4; t++) {
            atomicAdd(&s_st[4 * cx + t],       sq[t]);
            atomicAdd(&s_st[128 + 4 * cx + t], ss[t]);
        }
        __syncthreads();
        buf ^= 1;
    }

    // flush stats once per block
    if (tid < 128)      atomicAdd(&g_stats1[ch * 128 + tid],               s_st[tid]);
    else if (tid < 256) atomicAdd(&g_stats1[256 + ch * 128 + (tid - 128)], s_st[tid]);
}

// ---------------- kernel D: BN1 + sigmoid*softplus + sum_j, + BN2 stats ----
// 16 atoms per block, 256 threads: cx = channel quad (float4), grp -> 2 atoms.
__global__ void __launch_bounds__(256) kernelD(
    const float* __restrict__ mask,
    const float* __restrict__ gamma1, const float* __restrict__ beta1)
{
    __shared__ float s2[256];

    const int tid   = threadIdx.x;
    const int cx    = tid & 31;          // channel quad c = 4*cx (0..124)
    const int grp   = tid >> 5;          // 0..7, each handles 2 atoms
    const int atom0 = blockIdx.x * 16;
    const int c     = 4 * cx;

    s2[tid] = 0.f;

    const float inv_cnt = __fdividef(1.f, g_stats1[512]);
    float4 Sf  = *(const float4*)(g_stats1 + c);
    float4 Sc  = *(const float4*)(g_stats1 + 128 + c);
    float4 SSf = *(const float4*)(g_stats1 + 256 + c);
    float4 SSc = *(const float4*)(g_stats1 + 256 + 128 + c);
    float4 gf  = *(const float4*)(gamma1 + c);
    float4 gc  = *(const float4*)(gamma1 + 128 + c);
    float4 bf  = *(const float4*)(beta1 + c);
    float4 bcr = *(const float4*)(beta1 + 128 + c);

    float4 mf = make_float4(Sf.x * inv_cnt, Sf.y * inv_cnt, Sf.z * inv_cnt, Sf.w * inv_cnt);
    float4 mc = make_float4(Sc.x * inv_cnt, Sc.y * inv_cnt, Sc.z * inv_cnt, Sc.w * inv_cnt);
    float4 sf = make_float4(rsqrtf(SSf.x * inv_cnt - mf.x * mf.x + BN_EPS) * gf.x,
                            rsqrtf(SSf.y * inv_cnt - mf.y * mf.y + BN_EPS) * gf.y,
                            rsqrtf(SSf.z * inv_cnt - mf.z * mf.z + BN_EPS) * gf.z,
                            rsqrtf(SSf.w * inv_cnt - mf.w * mf.w + BN_EPS) * gf.w);
    float4 sc = make_float4(rsqrtf(SSc.x * inv_cnt - mc.x * mc.x + BN_EPS) * gc.x,
                            rsqrtf(SSc.y * inv_cnt - mc.y * mc.y + BN_EPS) * gc.y,
                            rsqrtf(SSc.z * inv_cnt - mc.z * mc.z + BN_EPS) * gc.z,
                            rsqrtf(SSc.w * inv_cnt - mc.w * mc.w + BN_EPS) * gc.w);
    __syncthreads();

    float4 sloc  = make_float4(0.f, 0.f, 0.f, 0.f);
    float4 ssloc = make_float4(0.f, 0.f, 0.f, 0.f);

    #pragma unroll
    for (int a = 0; a < 2; a++) {
        const int i = atom0 + grp * 2 + a;
        float m[12];
        #pragma unroll
        for (int j = 0; j < 12; j++) m[j] = __ldg(mask + i * 12 + j);

        float4 accv = make_float4(0.f, 0.f, 0.f, 0.f);
        #pragma unroll
        for (int half = 0; half < 2; half++) {
            float4 vf[6], vc[6];
            #pragma unroll
            for (int j = 0; j < 6; j++) {               // 12 predicated LDG.128 in flight
                int jj = half * 6 + j;
                const float* gp = g_gated + (size_t)(i * 12 + jj) * 256;
                bool act = (m[jj] != 0.f);
                vf[j] = act ? *(const float4*)(gp + c)       : make_float4(0.f, 0.f, 0.f, 0.f);
                vc[j] = act ? *(const float4*)(gp + 128 + c) : make_float4(0.f, 0.f, 0.f, 0.f);
            }
            #pragma unroll
            for (int j = 0; j < 6; j++) {
                int jj = half * 6 + j;
                if (m[jj] != 0.f) {
                    float hf0 = (vf[j].x - mf.x) * sf.x + bf.x;
                    float hf1 = (vf[j].y - mf.y) * sf.y + bf.y;
                    float hf2 = (vf[j].z - mf.z) * sf.z + bf.z;
                    float hf3 = (vf[j].w - mf.w) * sf.w + bf.w;
                    float hc0 = (vc[j].x - mc.x) * sc.x + bcr.x;
                    float hc1 = (vc[j].y - mc.y) * sc.y + bcr.y;
                    float hc2 = (vc[j].z - mc.z) * sc.z + bcr.z;
                    float hc3 = (vc[j].w - mc.w) * sc.w + bcr.w;
                    accv.x += sigmoid_fast(hf0) * softplus_fast(hc0);
                    accv.y += sigmoid_fast(hf1) * softplus_fast(hc1);
                    accv.z += sigmoid_fast(hf2) * softplus_fast(hc2);
                    accv.w += sigmoid_fast(hf3) * softplus_fast(hc3);
                }
            }
        }
        *(float4*)(g_nbrsum + (size_t)i * 128 + c) = accv;
        sloc.x  += accv.x; sloc.y  += accv.y; sloc.z  += accv.z; sloc.w  += accv.w;
        ssloc.x  = fmaf(accv.x, accv.x, ssloc.x);
        ssloc.y  = fmaf(accv.y, accv.y, ssloc.y);
        ssloc.z  = fmaf(accv.z, accv.z, ssloc.z);
        ssloc.w  = fmaf(accv.w, accv.w, ssloc.w);
    }
    atomicAdd(&s2[c + 0], sloc.x);  atomicAdd(&s2[c + 1], sloc.y);
    atomicAdd(&s2[c + 2], sloc.z);  atomicAdd(&s2[c + 3], sloc.w);
    atomicAdd(&s2[128 + c + 0], ssloc.x);  atomicAdd(&s2[128 + c + 1], ssloc.y);
    atomicAdd(&s2[128 + c + 2], ssloc.z);  atomicAdd(&s2[128 + c + 3], ssloc.w);
    __syncthreads();
    atomicAdd(&g_stats2[tid], s2[tid]);
}

// ---------------- kernel F: out = softplus(atom + BN2(nbrsum)) ----------------
__global__ void __launch_bounds__(256) kernelF(
    const float* __restrict__ atom,
    const float* __restrict__ gamma2, const float* __restrict__ beta2,
    float* __restrict__ out)
{
    int t = blockIdx.x * 256 + threadIdx.x;
    if (t >= N_ATOMS * 128) return;
    int c = t & 127;
    const float invN = 1.f / (float)N_ATOMS;
    float mean = g_stats2[c] * invN;
    float var  = g_stats2[128 + c] * invN - mean * mean;
    float x = (g_nbrsum[t] - mean) * rsqrtf(var + BN_EPS) * gamma2[c] + beta2[c];
    out[t] = softplus_fast(atom[t] + x);
}

// ---------------- launch ----------------
extern "C" void kernel_launch(void* const* d_in, const int* in_sizes, int n_in,
                              void* d_out, int out_size)
{
    const float* atom   = (const float*)d_in[0];
    const float* nbr    = (const float*)d_in[1];
    const int*   idx    = (const int*)  d_in[2];
    const float* mask   = (const float*)d_in[3];
    const float* W      = (const float*)d_in[4];
    const float* bias   = (const float*)d_in[5];
    const float* gamma1 = (const float*)d_in[6];
    const float* beta1  = (const float*)d_in[7];
    const float* gamma2 = (const float*)d_in[8];
    const float* beta2  = (const float*)d_in[9];
    float* out = (float*)d_out;

    cudaFuncSetAttribute(gemmA_kernel, cudaFuncAttributeMaxDynamicSharedMemorySize, SMEM_A_BYTES);
    cudaFuncSetAttribute(kernelB,      cudaFuncAttributeMaxDynamicSharedMemorySize, SMEM_B_BYTES);

    zero_stats_kernel<<<1, 1024>>>();
    compact_kernel<<<(N_ROWS + 255) / 256, 256>>>(mask);
    gemmA_kernel<<<dim3((N_ATOMS + 63) / 64, 2), 256, SMEM_A_BYTES>>>(atom, W, bias);
    kernelB<<<NB_B, 256, SMEM_B_BYTES>>>(nbr, idx, W);
    kernelD<<<N_ATOMS / 16, 256>>>(mask, gamma1, beta1);
    kernelF<<<(N_ATOMS * 128) / 256, 256>>>(atom, gamma2, beta2, out);
}